// round 1
// baseline (speedup 1.0000x reference)
#include <cuda_runtime.h>
#include <math.h>

// ---------------- problem constants ----------------
#define BATCH 128
#define C1 256          // conv1 out channels
#define H1 20           // conv1 out spatial
#define C2 256          // conv2 out channels
#define H2 12           // conv2 out spatial
#define NMAP 32
#define NPRIM 144       // 12*12
#define NCAP (NMAP*NPRIM)   // 4608
#define NCLS 10
#define OD 16
#define ID 8

#define OUT_OHE_OFF 0
#define OUT_REC_OFF (BATCH*NCLS)                    // 1280
#define OUT_LEN_OFF (BATCH*NCLS + BATCH*784)        // 101632

// ---------------- device scratch (static allocation, rules-compliant) ----------------
__device__ float g_conv1[(size_t)BATCH*C1*H1*H1];            // 13.1M f
__device__ float g_p[(size_t)BATCH*C2*H2*H2];                // 4.7M f
__device__ float g_u[(size_t)BATCH*NCAP*ID];                 // 4.7M f
__device__ float g_uhat[(size_t)BATCH*NCAP*NCLS*OD];         // 94.4M f (377MB)
__device__ float g_bij[(size_t)BATCH*NCAP*NCLS];             // 5.9M f
__device__ float g_v[BATCH*NCLS*OD];
__device__ int   g_cls[BATCH];
__device__ float g_h1[BATCH*512];
__device__ float g_h2[BATCH*1024];

// ---------------- conv1 + relu ----------------
// block = (oc, b), 256 threads; smem img + weights
__global__ __launch_bounds__(256) void conv1_kernel(
    const float* __restrict__ img, const float* __restrict__ w,
    const float* __restrict__ bias)
{
    int oc = blockIdx.x, b = blockIdx.y;
    __shared__ float si[28*28];
    __shared__ float sw[81];
    int t = threadIdx.x;
    for (int i = t; i < 784; i += 256) si[i] = img[b*784 + i];
    if (t < 81) sw[t] = w[oc*81 + t];
    __syncthreads();
    float bs = bias[oc];
    for (int pos = t; pos < 400; pos += 256) {
        int oy = pos / 20, ox = pos % 20;
        float a = 0.f;
        #pragma unroll
        for (int ky = 0; ky < 9; ky++) {
            #pragma unroll
            for (int kx = 0; kx < 9; kx++)
                a = fmaf(sw[ky*9+kx], si[(oy+ky)*28 + ox + kx], a);
        }
        a += bs;
        g_conv1[(((size_t)b*C1 + oc)*H1 + oy)*H1 + ox] = fmaxf(a, 0.f);
    }
}

// ---------------- conv2 (primary caps conv, no relu) ----------------
// block = (octile of 16, b); thread = (oc_local, oy); 12 ox accumulators in regs
#define ICB 4
__global__ __launch_bounds__(192) void conv2_kernel(
    const float* __restrict__ w2, const float* __restrict__ b2)
{
    int octile = blockIdx.x;            // 0..15
    int b = blockIdx.y;
    int t = threadIdx.x;                // 0..191
    int oc_l = t / 12;                  // 0..15
    int oy   = t % 12;

    __shared__ float xs[ICB][400];      // 6.4 KB
    __shared__ float ws[16][ICB][81];   // 20.7 KB

    float acc[12];
    #pragma unroll
    for (int i = 0; i < 12; i++) acc[i] = 0.f;

    const float* xin = g_conv1 + (size_t)b*C1*400;

    for (int ic0 = 0; ic0 < C1; ic0 += ICB) {
        __syncthreads();
        for (int i = t; i < ICB*400; i += 192) {
            int ic = i / 400, r = i % 400;
            xs[ic][r] = xin[(size_t)(ic0 + ic)*400 + r];
        }
        for (int i = t; i < 16*ICB*81; i += 192) {
            int oc = i / (ICB*81), r = i % (ICB*81);
            int ic = r / 81, k = r % 81;
            ws[oc][ic][k] = w2[((size_t)(octile*16 + oc)*C1 + ic0 + ic)*81 + k];
        }
        __syncthreads();

        #pragma unroll 1
        for (int ic = 0; ic < ICB; ic++) {
            #pragma unroll 1
            for (int ky = 0; ky < 9; ky++) {
                float xr[20];
                #pragma unroll
                for (int i = 0; i < 20; i++) xr[i] = xs[ic][(oy+ky)*20 + i];
                #pragma unroll
                for (int kx = 0; kx < 9; kx++) {
                    float wv = ws[oc_l][ic][ky*9 + kx];
                    #pragma unroll
                    for (int ox = 0; ox < 12; ox++)
                        acc[ox] = fmaf(wv, xr[ox + kx], acc[ox]);
                }
            }
        }
    }

    int oc = octile*16 + oc_l;
    float bv = b2[oc];
    #pragma unroll
    for (int ox = 0; ox < 12; ox++)
        g_p[(((size_t)b*C2 + oc)*H2 + oy)*H2 + ox] = acc[ox] + bv;
}

// ---------------- primary capsule squash ----------------
// p[b, d*32+m, pos] -> u[b, m, pos, d], squash over d
__global__ void squash_prim_kernel()
{
    int idx = blockIdx.x*blockDim.x + threadIdx.x;
    if (idx >= BATCH*NCAP) return;
    int pos = idx % NPRIM;
    int m   = (idx / NPRIM) % NMAP;
    int b   = idx / NCAP;
    float x[ID]; float s2 = 0.f;
    #pragma unroll
    for (int d = 0; d < ID; d++) {
        x[d] = g_p[(((size_t)b*C2 + d*NMAP + m)*NPRIM) + pos];
        s2 = fmaf(x[d], x[d], s2);
    }
    float scale = (s2 / (1.f + s2)) / sqrtf(s2 + 1e-8f);
    float* up = g_u + (size_t)idx*ID;
    #pragma unroll
    for (int d = 0; d < ID; d++) up[d] = scale * x[d];
}

// ---------------- u_hat = W[m,p,c,o,i] . u[b,m,p,i] ----------------
// block per input capsule n; W slice + all u[b] in smem
__global__ __launch_bounds__(256) void uhat_kernel(const float* __restrict__ Wd)
{
    int n = blockIdx.x;                 // 0..4607
    __shared__ float sW[NCLS*OD*ID];    // 1280 f
    __shared__ float su[BATCH][ID];     // 1024 f
    int t = threadIdx.x;
    for (int i = t; i < NCLS*OD*ID; i += 256) sW[i] = Wd[(size_t)n*NCLS*OD*ID + i];
    for (int i = t; i < BATCH*ID; i += 256) {
        int b = i / ID, d = i % ID;
        su[b][d] = g_u[((size_t)b*NCAP + n)*ID + d];
    }
    __syncthreads();
    for (int it = t; it < BATCH*NCLS*OD; it += 256) {
        int co = it % (NCLS*OD);
        int b  = it / (NCLS*OD);
        const float* wr = &sW[co*ID];
        const float* uu = su[b];
        float a = 0.f;
        #pragma unroll
        for (int i = 0; i < ID; i++) a = fmaf(wr[i], uu[i], a);
        g_uhat[((size_t)b*NCAP + n)*(NCLS*OD) + co] = a;
    }
}

// ---------------- routing ----------------
__global__ void bij_zero_kernel()
{
    size_t idx = (size_t)blockIdx.x*256 + threadIdx.x;
    if (idx < (size_t)BATCH*NCAP*NCLS) g_bij[idx] = 0.f;
}

// per (b, c): softmax over n, s_j accumulation, squash -> v
__global__ __launch_bounds__(256) void route_sj_kernel()
{
    int c = blockIdx.x, b = blockIdx.y;
    int t = threadIdx.x;
    __shared__ float red[256];
    __shared__ float wsum[8][16];

    // cache this thread's 18 logits
    float bl[18];
    #pragma unroll
    for (int j = 0; j < 18; j++)
        bl[j] = g_bij[((size_t)b*NCAP + t + j*256)*NCLS + c];

    // max over n
    float m = bl[0];
    #pragma unroll
    for (int j = 1; j < 18; j++) m = fmaxf(m, bl[j]);
    red[t] = m; __syncthreads();
    for (int s = 128; s > 0; s >>= 1) {
        if (t < s) red[t] = fmaxf(red[t], red[t+s]);
        __syncthreads();
    }
    float bmax = red[0]; __syncthreads();

    // sumexp
    float se = 0.f;
    #pragma unroll
    for (int j = 0; j < 18; j++) { bl[j] = expf(bl[j] - bmax); se += bl[j]; }
    red[t] = se; __syncthreads();
    for (int s = 128; s > 0; s >>= 1) {
        if (t < s) red[t] += red[t+s];
        __syncthreads();
    }
    float inv = 1.f / red[0];

    // s_j = sum_n c_n * u_hat[b,n,c,:]
    float sc[16];
    #pragma unroll
    for (int o = 0; o < 16; o++) sc[o] = 0.f;
    #pragma unroll 1
    for (int j = 0; j < 18; j++) {
        int n = t + j*256;
        float cn = bl[j] * inv;
        const float4* uh = (const float4*)&g_uhat[(((size_t)b*NCAP + n)*NCLS + c)*OD];
        float4 a0 = uh[0], a1 = uh[1], a2 = uh[2], a3 = uh[3];
        sc[0]  = fmaf(cn, a0.x, sc[0]);  sc[1]  = fmaf(cn, a0.y, sc[1]);
        sc[2]  = fmaf(cn, a0.z, sc[2]);  sc[3]  = fmaf(cn, a0.w, sc[3]);
        sc[4]  = fmaf(cn, a1.x, sc[4]);  sc[5]  = fmaf(cn, a1.y, sc[5]);
        sc[6]  = fmaf(cn, a1.z, sc[6]);  sc[7]  = fmaf(cn, a1.w, sc[7]);
        sc[8]  = fmaf(cn, a2.x, sc[8]);  sc[9]  = fmaf(cn, a2.y, sc[9]);
        sc[10] = fmaf(cn, a2.z, sc[10]); sc[11] = fmaf(cn, a2.w, sc[11]);
        sc[12] = fmaf(cn, a3.x, sc[12]); sc[13] = fmaf(cn, a3.y, sc[13]);
        sc[14] = fmaf(cn, a3.z, sc[14]); sc[15] = fmaf(cn, a3.w, sc[15]);
    }
    // warp reduce each of 16
    #pragma unroll
    for (int o = 0; o < 16; o++) {
        #pragma unroll
        for (int off = 16; off > 0; off >>= 1)
            sc[o] += __shfl_down_sync(0xffffffffu, sc[o], off);
    }
    int warp = t >> 5, lane = t & 31;
    if (lane == 0) {
        #pragma unroll
        for (int o = 0; o < 16; o++) wsum[warp][o] = sc[o];
    }
    __syncthreads();
    if (t < 16) {
        float v = 0.f;
        #pragma unroll
        for (int w = 0; w < 8; w++) v += wsum[w][t];
        float s2 = v * v;
        #pragma unroll
        for (int off = 8; off > 0; off >>= 1)
            s2 += __shfl_down_sync(0xffffu, s2, off);
        s2 = __shfl_sync(0xffffu, s2, 0);
        float scale = (s2 / (1.f + s2)) / sqrtf(s2 + 1e-8f);
        g_v[(b*NCLS + c)*OD + t] = scale * v;
    }
}

// b_ij += dot(u_hat[b,n,c,:], v[b,c,:])
__global__ void route_agree_kernel()
{
    size_t idx = (size_t)blockIdx.x*256 + threadIdx.x;
    if (idx >= (size_t)BATCH*NCAP*NCLS) return;
    int c = idx % NCLS;
    int b = (int)(idx / ((size_t)NCAP*NCLS));
    const float4* uh = (const float4*)&g_uhat[idx*OD];
    const float4* vv = (const float4*)&g_v[(b*NCLS + c)*OD];
    float a = 0.f;
    #pragma unroll
    for (int q = 0; q < 4; q++) {
        float4 u4 = uh[q], v4 = vv[q];
        a = fmaf(u4.x, v4.x, a); a = fmaf(u4.y, v4.y, a);
        a = fmaf(u4.z, v4.z, a); a = fmaf(u4.w, v4.w, a);
    }
    g_bij[idx] += a;
}

// ---------------- head: lengths, argmax (first max), one-hot, masked select ----------------
__global__ void head_kernel(float* __restrict__ out)
{
    int b = blockIdx.x;
    int t = threadIdx.x;   // 32
    __shared__ float len[NCLS];
    if (t < NCLS) {
        float s = 0.f;
        #pragma unroll
        for (int o = 0; o < OD; o++) {
            float x = g_v[(b*NCLS + t)*OD + o];
            s = fmaf(x, x, s);
        }
        len[t] = sqrtf(s);
    }
    __syncthreads();
    if (t == 0) {
        int best = 0; float bv = len[0];
        #pragma unroll
        for (int c = 1; c < NCLS; c++)
            if (len[c] > bv) { bv = len[c]; best = c; }
        g_cls[b] = best;
    }
    __syncthreads();
    int best = g_cls[b];
    if (t < NCLS) {
        out[OUT_OHE_OFF + b*NCLS + t] = (t == best) ? 1.0f : 0.0f;
        out[OUT_LEN_OFF + b*NCLS + t] = len[t];
    }
}

// ---------------- decoder ----------------
__global__ void dec1_kernel(const float* __restrict__ w1, const float* __restrict__ b1)
{
    int idx = blockIdx.x*256 + threadIdx.x;       // BATCH*512
    if (idx >= BATCH*512) return;
    int j = idx % 512, b = idx / 512;
    int cls = g_cls[b];
    const float* v = &g_v[(b*NCLS + cls)*OD];
    float a = b1[j];
    #pragma unroll
    for (int d = 0; d < OD; d++)
        a = fmaf(v[d], w1[(size_t)(cls*OD + d)*512 + j], a);
    g_h1[idx] = fmaxf(a, 0.f);
}

__global__ void dec2_kernel(const float* __restrict__ w2, const float* __restrict__ b2)
{
    int idx = blockIdx.x*256 + threadIdx.x;       // BATCH*1024
    if (idx >= BATCH*1024) return;
    int j = idx % 1024, b = idx / 1024;
    const float* h = &g_h1[b*512];
    float a = b2[j];
    #pragma unroll 4
    for (int k = 0; k < 512; k++)
        a = fmaf(h[k], w2[(size_t)k*1024 + j], a);
    g_h2[idx] = fmaxf(a, 0.f);
}

__global__ void dec3_kernel(const float* __restrict__ w3, const float* __restrict__ b3,
                            float* __restrict__ out)
{
    int idx = blockIdx.x*256 + threadIdx.x;       // BATCH*784
    if (idx >= BATCH*784) return;
    int p = idx % 784, b = idx / 784;
    const float* h = &g_h2[b*1024];
    float a = b3[p];
    #pragma unroll 4
    for (int k = 0; k < 1024; k++)
        a = fmaf(h[k], w3[(size_t)k*784 + p], a);
    out[OUT_REC_OFF + idx] = 1.f / (1.f + expf(-a));
}

// ---------------- launch ----------------
extern "C" void kernel_launch(void* const* d_in, const int* in_sizes, int n_in,
                              void* d_out, int out_size)
{
    const float* imgs    = (const float*)d_in[0];
    const float* conv1_w = (const float*)d_in[1];
    const float* conv1_b = (const float*)d_in[2];
    const float* conv2_w = (const float*)d_in[3];
    const float* conv2_b = (const float*)d_in[4];
    const float* W_digit = (const float*)d_in[5];
    const float* dec_w1  = (const float*)d_in[6];
    const float* dec_b1  = (const float*)d_in[7];
    const float* dec_w2  = (const float*)d_in[8];
    const float* dec_b2  = (const float*)d_in[9];
    const float* dec_w3  = (const float*)d_in[10];
    const float* dec_b3  = (const float*)d_in[11];
    float* out = (float*)d_out;

    // conv1 + relu
    conv1_kernel<<<dim3(C1, BATCH), 256>>>(imgs, conv1_w, conv1_b);
    // conv2
    conv2_kernel<<<dim3(16, BATCH), 192>>>(conv2_w, conv2_b);
    // primary squash
    {
        int n = BATCH*NCAP;
        squash_prim_kernel<<<(n + 255)/256, 256>>>();
    }
    // u_hat
    uhat_kernel<<<NCAP, 256>>>(W_digit);
    // routing
    {
        size_t n = (size_t)BATCH*NCAP*NCLS;
        int blk = (int)((n + 255)/256);
        bij_zero_kernel<<<blk, 256>>>();
        for (int it = 0; it < 3; it++) {
            route_sj_kernel<<<dim3(NCLS, BATCH), 256>>>();
            if (it != 2) route_agree_kernel<<<blk, 256>>>();
        }
    }
    // head + decoder
    head_kernel<<<BATCH, 32>>>(out);
    dec1_kernel<<<(BATCH*512 + 255)/256, 256>>>(dec_w1, dec_b1);
    dec2_kernel<<<(BATCH*1024 + 255)/256, 256>>>(dec_w2, dec_b2);
    dec3_kernel<<<(BATCH*784 + 255)/256, 256>>>(dec_w3, dec_b3, out);
    (void)in_sizes; (void)n_in; (void)out_size;
}